// round 13
// baseline (speedup 1.0000x reference)
#include <cuda_runtime.h>
#include <cuda_bf16.h>
#include <mma.h>
#include <cstdint>

using namespace nvcuda;

#define N_NODES 40000
#define N_EDGES 640000
#define DIN 128
#define DH 128
#define DOUT 64
#define PAD 64                                      // max in-degree slots per node

#define NT ((N_NODES + 127) / 128)                   // 313 M-tiles
#define GEMM_GRID 152

// ---------------- scratch (no allocations allowed) ----------------
__device__ int   g_is64;
__device__ int   g_cnt[N_NODES];
__device__ __align__(16) int g_eslots[(size_t)N_NODES * PAD];   // padded adjacency (src ids)
__device__ float g_dinv[N_NODES];
__device__ float g_h1[(size_t)N_NODES * DH];         // gemm1 out (fp32)
__device__ float g_agg1[(size_t)N_NODES * DH];       // relu(agg + b1) fp32
__device__ float g_h2[(size_t)N_NODES * DOUT];       // gemm2 out (fp32)
// weights bf16 hi/lo, row-major [k][n]
__device__ __align__(16) __nv_bfloat16 g_b1hi[DIN * DH];
__device__ __align__(16) __nv_bfloat16 g_b1lo[DIN * DH];
__device__ __align__(16) __nv_bfloat16 g_b2hi[DH * DOUT];
__device__ __align__(16) __nv_bfloat16 g_b2lo[DH * DOUT];

// ---------------- init: zero counts + dtype detect + weight split (fused) ----------------
__global__ void k_init(const int* __restrict__ ei,
                       const float* __restrict__ W1, const float* __restrict__ W2) {
    int i = blockIdx.x * blockDim.x + threadIdx.x;
    if (i < N_NODES) g_cnt[i] = 0;
    // weight hi/lo split (24576 elements)
    if (i < DIN * DH) {
        float v = W1[i];
        __nv_bfloat16 h = __float2bfloat16(v);
        g_b1hi[i] = h;
        g_b1lo[i] = __float2bfloat16(v - __bfloat162float(h));
    }
    int j = i - DIN * DH;
    if (j >= 0 && j < DH * DOUT) {
        float v = W2[j];
        __nv_bfloat16 h = __float2bfloat16(v);
        g_b2hi[j] = h;
        g_b2lo[j] = __float2bfloat16(v - __bfloat162float(h));
    }
    // dtype detect: int64 indices < 2^31 => odd int32 words of first 4096 pairs all zero
    if (blockIdx.x == 0) {
        __shared__ int any_nz;
        if (threadIdx.x == 0) any_nz = 0;
        __syncthreads();
        int nz = 0;
        for (int t = threadIdx.x; t < 4096; t += blockDim.x)
            if (ei[2 * t + 1] != 0) nz = 1;
        if (nz) any_nz = 1;
        __syncthreads();
        if (threadIdx.x == 0) g_is64 = any_nz ? 0 : 1;
    }
}

__device__ __forceinline__ int edge_idx(const void* ei, int which, int e, int is64) {
    if (is64) return (int)((const long long*)ei)[(size_t)which * N_EDGES + e];
    return ((const int*)ei)[which * N_EDGES + e];
}

// ---------------- direct padded-list fill (no count/scan needed) ----------------
__global__ void k_fill(const void* __restrict__ ei) {
    int e = blockIdx.x * blockDim.x + threadIdx.x;
    if (e < N_EDGES) {
        int is64 = g_is64;
        int d = edge_idx(ei, 1, e, is64);
        int s = edge_idx(ei, 0, e, is64);
        if ((unsigned)d < N_NODES && (unsigned)s < N_NODES) {
            int pos = atomicAdd(&g_cnt[d], 1);
            if (pos < PAD) g_eslots[(size_t)d * PAD + pos] = s;
        }
    }
}

__global__ void k_dinv() {
    int i = blockIdx.x * blockDim.x + threadIdx.x;
    if (i < N_NODES) g_dinv[i] = rsqrtf((float)(g_cnt[i] + 1));   // +1 self-loop
}

// ---------------- WMMA bf16 GEMM: C[40000,N] = A[40000,128] @ B[128,N] ----------------
// A fp32 in GMEM, split to bf16 hi/lo during SMEM staging.
// fp32 accum: acc += Ah*Bh + Ah*Bl + Al*Bh. Persistent blocks; B SMEM-resident.
__device__ __forceinline__ void split2(float a, float b, uint32_t& hi, uint32_t& lo) {
    __nv_bfloat16 ha = __float2bfloat16(a), hb = __float2bfloat16(b);
    float ra = a - __bfloat162float(ha), rb = b - __bfloat162float(hb);
    __nv_bfloat16 la = __float2bfloat16(ra), lb = __float2bfloat16(rb);
    hi = (uint32_t)__bfloat16_as_ushort(ha) | ((uint32_t)__bfloat16_as_ushort(hb) << 16);
    lo = (uint32_t)__bfloat16_as_ushort(la) | ((uint32_t)__bfloat16_as_ushort(lb) << 16);
}

template <int N>
__global__ void __launch_bounds__(256, 1) k_gemm_wmma(
    const float* __restrict__ A,
    const __nv_bfloat16* __restrict__ Bhi, const __nv_bfloat16* __restrict__ Blo,
    float* __restrict__ C) {
    constexpr int K = 128, BM = 128;
    constexpr int LDA = K + 8;
    constexpr int LDB = N + 8;
    extern __shared__ __nv_bfloat16 sm[];
    __nv_bfloat16* sAh = sm;
    __nv_bfloat16* sAl = sAh + BM * LDA;
    __nv_bfloat16* sBh = sAl + BM * LDA;
    __nv_bfloat16* sBl = sBh + K * LDB;

    const int tid = threadIdx.x, wid = tid >> 5;

    constexpr int NQ = N / 8;
    for (int idx = tid; idx < K * NQ; idx += 256) {
        int r = idx / NQ, cq = idx % NQ;
        *(uint4*)(sBh + r * LDB + cq * 8) = ((const uint4*)(Bhi + (size_t)r * N))[cq];
        *(uint4*)(sBl + r * LDB + cq * 8) = ((const uint4*)(Blo + (size_t)r * N))[cq];
    }

    constexpr int WN = (N == 128) ? 64 : 32;
    constexpr int NFRAG = WN / 16;
    const int wm = (wid >> 1) * 32;
    const int wn = (wid & 1) * WN;

    for (int t = blockIdx.x; t < NT; t += gridDim.x) {
        int row0 = t * BM;
#pragma unroll
        for (int p = 0; p < 16; p++) {
            int idx = p * 256 + tid;
            int r = idx >> 5;
            int cq = idx & 31;
            int grow = row0 + r;
            float4 v = make_float4(0.f, 0.f, 0.f, 0.f);
            if (grow < N_NODES) v = ((const float4*)(A + (size_t)grow * K))[cq];
            uint2 h, l;
            split2(v.x, v.y, h.x, l.x);
            split2(v.z, v.w, h.y, l.y);
            *(uint2*)(sAh + r * LDA + cq * 4) = h;
            *(uint2*)(sAl + r * LDA + cq * 4) = l;
        }
        __syncthreads();

        wmma::fragment<wmma::accumulator, 16, 16, 16, float> acc[2][NFRAG];
#pragma unroll
        for (int i = 0; i < 2; i++)
#pragma unroll
            for (int j = 0; j < NFRAG; j++) wmma::fill_fragment(acc[i][j], 0.0f);

#pragma unroll
        for (int k = 0; k < K; k += 16) {
            wmma::fragment<wmma::matrix_a, 16, 16, 16, __nv_bfloat16, wmma::row_major> ah[2], al[2];
#pragma unroll
            for (int i = 0; i < 2; i++) {
                wmma::load_matrix_sync(ah[i], sAh + (wm + i * 16) * LDA + k, LDA);
                wmma::load_matrix_sync(al[i], sAl + (wm + i * 16) * LDA + k, LDA);
            }
#pragma unroll
            for (int j = 0; j < NFRAG; j++) {
                wmma::fragment<wmma::matrix_b, 16, 16, 16, __nv_bfloat16, wmma::row_major> bh, bl;
                wmma::load_matrix_sync(bh, sBh + k * LDB + wn + j * 16, LDB);
                wmma::load_matrix_sync(bl, sBl + k * LDB + wn + j * 16, LDB);
#pragma unroll
                for (int i = 0; i < 2; i++) {
                    wmma::mma_sync(acc[i][j], ah[i], bh, acc[i][j]);
                    wmma::mma_sync(acc[i][j], ah[i], bl, acc[i][j]);
                    wmma::mma_sync(acc[i][j], al[i], bh, acc[i][j]);
                }
            }
        }

#pragma unroll
        for (int i = 0; i < 2; i++) {
            int grow = row0 + wm + i * 16;
            if (grow < N_NODES) {
#pragma unroll
                for (int j = 0; j < NFRAG; j++)
                    wmma::store_matrix_sync(C + (size_t)grow * N + wn + j * 16, acc[i][j],
                                            N, wmma::mem_row_major);
            }
        }
        __syncthreads();
    }
}

// ---------------- gather layer 1: one warp per node; emits relu(agg+b1) fp32 ----------------
__global__ void k_gather1(const float* __restrict__ b1) {
    int node = (blockIdx.x * blockDim.x + threadIdx.x) >> 5;
    if (node >= N_NODES) return;
    int lane = threadIdx.x & 31;

    float dd = g_dinv[node];
    float self = dd * dd;
    float4 acc = ((const float4*)(g_h1 + (size_t)node * DH))[lane];
    acc.x *= self; acc.y *= self; acc.z *= self; acc.w *= self;

    int n = min(g_cnt[node], PAD);
    const int* lst = g_eslots + (size_t)node * PAD;   // 256B aligned
    int e = 0;
    for (; e + 4 <= n; e += 4) {
        int4 s4 = *(const int4*)(lst + e);
        float w0 = g_dinv[s4.x] * dd, w1 = g_dinv[s4.y] * dd;
        float w2 = g_dinv[s4.z] * dd, w3 = g_dinv[s4.w] * dd;
        float4 v0 = ((const float4*)(g_h1 + (size_t)s4.x * DH))[lane];
        float4 v1 = ((const float4*)(g_h1 + (size_t)s4.y * DH))[lane];
        float4 v2 = ((const float4*)(g_h1 + (size_t)s4.z * DH))[lane];
        float4 v3 = ((const float4*)(g_h1 + (size_t)s4.w * DH))[lane];
        acc.x = fmaf(v0.x, w0, fmaf(v1.x, w1, fmaf(v2.x, w2, fmaf(v3.x, w3, acc.x))));
        acc.y = fmaf(v0.y, w0, fmaf(v1.y, w1, fmaf(v2.y, w2, fmaf(v3.y, w3, acc.y))));
        acc.z = fmaf(v0.z, w0, fmaf(v1.z, w1, fmaf(v2.z, w2, fmaf(v3.z, w3, acc.z))));
        acc.w = fmaf(v0.w, w0, fmaf(v1.w, w1, fmaf(v2.w, w2, fmaf(v3.w, w3, acc.w))));
    }
    for (; e < n; e++) {
        int s = lst[e];
        float w = g_dinv[s] * dd;
        float4 v = ((const float4*)(g_h1 + (size_t)s * DH))[lane];
        acc.x = fmaf(v.x, w, acc.x);
        acc.y = fmaf(v.y, w, acc.y);
        acc.z = fmaf(v.z, w, acc.z);
        acc.w = fmaf(v.w, w, acc.w);
    }
    float4 bb = ((const float4*)b1)[lane];
    acc.x = fmaxf(acc.x + bb.x, 0.0f);
    acc.y = fmaxf(acc.y + bb.y, 0.0f);
    acc.z = fmaxf(acc.z + bb.z, 0.0f);
    acc.w = fmaxf(acc.w + bb.w, 0.0f);
    ((float4*)(g_agg1 + (size_t)node * DH))[lane] = acc;
}

// ---------------- gather layer 2 (C=64): half-warp per node, + b2 ----------------
__global__ void k_gather2(const float* __restrict__ b2, float* __restrict__ out) {
    int gw = (blockIdx.x * blockDim.x + threadIdx.x) >> 5;
    int lane = threadIdx.x & 31;
    int node = gw * 2 + (lane >> 4);
    if (node >= N_NODES) return;
    int l = lane & 15;

    float dd = g_dinv[node];
    float self = dd * dd;
    float4 acc = ((const float4*)(g_h2 + (size_t)node * DOUT))[l];
    acc.x *= self; acc.y *= self; acc.z *= self; acc.w *= self;

    int n = min(g_cnt[node], PAD);
    const int* lst = g_eslots + (size_t)node * PAD;
    int e = 0;
    for (; e + 4 <= n; e += 4) {
        int4 s4 = *(const int4*)(lst + e);
        float w0 = g_dinv[s4.x] * dd, w1 = g_dinv[s4.y] * dd;
        float w2 = g_dinv[s4.z] * dd, w3 = g_dinv[s4.w] * dd;
        float4 v0 = ((const float4*)(g_h2 + (size_t)s4.x * DOUT))[l];
        float4 v1 = ((const float4*)(g_h2 + (size_t)s4.y * DOUT))[l];
        float4 v2 = ((const float4*)(g_h2 + (size_t)s4.z * DOUT))[l];
        float4 v3 = ((const float4*)(g_h2 + (size_t)s4.w * DOUT))[l];
        acc.x = fmaf(v0.x, w0, fmaf(v1.x, w1, fmaf(v2.x, w2, fmaf(v3.x, w3, acc.x))));
        acc.y = fmaf(v0.y, w0, fmaf(v1.y, w1, fmaf(v2.y, w2, fmaf(v3.y, w3, acc.y))));
        acc.z = fmaf(v0.z, w0, fmaf(v1.z, w1, fmaf(v2.z, w2, fmaf(v3.z, w3, acc.z))));
        acc.w = fmaf(v0.w, w0, fmaf(v1.w, w1, fmaf(v2.w, w2, fmaf(v3.w, w3, acc.w))));
    }
    for (; e < n; e++) {
        int s = lst[e];
        float w = g_dinv[s] * dd;
        float4 v = ((const float4*)(g_h2 + (size_t)s * DOUT))[l];
        acc.x = fmaf(v.x, w, acc.x);
        acc.y = fmaf(v.y, w, acc.y);
        acc.z = fmaf(v.z, w, acc.z);
        acc.w = fmaf(v.w, w, acc.w);
    }
    float4 b = ((const float4*)b2)[l];
    acc.x += b.x; acc.y += b.y; acc.z += b.z; acc.w += b.w;
    ((float4*)(out + (size_t)node * DOUT))[l] = acc;
}

// ---------------- launch ----------------
extern "C" void kernel_launch(void* const* d_in, const int* in_sizes, int n_in,
                              void* d_out, int out_size) {
    const float* x  = (const float*)d_in[0];
    const void*  ei = d_in[1];
    const float* W1 = (const float*)d_in[2];
    const float* b1 = (const float*)d_in[3];
    const float* W2 = (const float*)d_in[4];
    const float* b2 = (const float*)d_in[5];
    float*       out = (float*)d_out;

    float *h1, *h2, *agg1;
    __nv_bfloat16 *b1hi, *b1lo, *b2hi, *b2lo;
    cudaGetSymbolAddress((void**)&h1, g_h1);
    cudaGetSymbolAddress((void**)&h2, g_h2);
    cudaGetSymbolAddress((void**)&agg1, g_agg1);
    cudaGetSymbolAddress((void**)&b1hi, g_b1hi);
    cudaGetSymbolAddress((void**)&b1lo, g_b1lo);
    cudaGetSymbolAddress((void**)&b2hi, g_b2hi);
    cudaGetSymbolAddress((void**)&b2lo, g_b2lo);

    const int SM1 = (2 * 128 * 136 + 2 * 128 * (DH + 8)) * 2;     // 139264 B
    const int SM2 = (2 * 128 * 136 + 2 * 128 * (DOUT + 8)) * 2;   // 106496 B
    cudaFuncSetAttribute(k_gemm_wmma<DH>,   cudaFuncAttributeMaxDynamicSharedMemorySize, SM1);
    cudaFuncSetAttribute(k_gemm_wmma<DOUT>, cudaFuncAttributeMaxDynamicSharedMemorySize, SM2);

    const int T = 256;

    // prep: zero counts + dtype detect + weight split, then padded-list fill + dinv
    k_init<<<(N_NODES + T - 1) / T, T>>>((const int*)ei, W1, W2);
    k_fill<<<(N_EDGES + T - 1) / T, T>>>(ei);
    k_dinv<<<(N_NODES + T - 1) / T, T>>>();

    // layer 1
    k_gemm_wmma<DH><<<GEMM_GRID, T, SM1>>>(x, b1hi, b1lo, h1);
    k_gather1<<<(N_NODES * 32 + T - 1) / T, T>>>(b1);

    // layer 2
    k_gemm_wmma<DOUT><<<GEMM_GRID, T, SM2>>>(agg1, b2hi, b2lo, h2);
    k_gather2<<<(N_NODES / 2 * 32 + T - 1) / T, T>>>(b2, out);
}